// round 10
// baseline (speedup 1.0000x reference)
#include <cuda_runtime.h>
#include <cuda_bf16.h>
#include <cuda_fp16.h>

// emb[b,f,e] = b2[f,e] + sum_h W2[f,e,h]*relu(x[b,f]*W1[f,h]+b1[f,h])
// Piecewise-linear-in-x: per f, 65 segments; emb = A(seg)*x + C(seg).
// fp16 segment row (64B): 8 x {half2 A, half2 C}.
// Segment lookup: 512-bucket LUT (uchar2 bounds) + rare exact refinement.

#define BN 16384
#define FN 128
#define HN 64
#define EN 16
#define THR_S 72        // threshold stride (bank spread across ff)
#define TAB_S 524       // smem table stride in h4 units
#define NB   512        // buckets
#define LUT_S 520       // smem lut stride

#define BUCK_LO (-6.0f)
#define BUCK_SC ((float)NB / 12.0f)

struct __align__(8) h4 { __half2 a, c; };

__device__ h4     g_tab_h[FN * 520];     // per f: 65 segs * 8 h4
__device__ float  g_thr[FN * 64];        // sorted hinge thresholds per f
__device__ uchar2 g_lutp[FN * (NB + 1)]; // (lut[k], lut[k+1])

__device__ __forceinline__ int bucket_of(float v) {
    float p = (v - BUCK_LO) * BUCK_SC;
    p = fminf(fmaxf(p, 0.0f), (float)(NB - 1));
    return (int)p;
}

// ---------------------------------------------------------------------------
// Kernel 1: per-feature precompute. One block per f, 128 threads.
// ---------------------------------------------------------------------------
__global__ void __launch_bounds__(128) dfe_precompute(
    const float* __restrict__ W1, const float* __restrict__ b1,
    const float* __restrict__ W2, const float* __restrict__ b2)
{
    int f = blockIdx.x;
    int tid = threadIdx.x;

    __shared__ float sw[HN], sb[HN], tv_[HN], st[HN];
    __shared__ int   sidx[HN];
    __shared__ float sv[EN * HN];
    __shared__ float stab[65 * 32];
    __shared__ unsigned char slutc[NB + 1];

    for (int i = tid; i < EN * HN; i += 128) sv[i] = W2[f * EN * HN + i];

    if (tid < HN) {
        float w = W1[f * HN + tid];
        float b = b1[f * HN + tid];
        sw[tid] = w; sb[tid] = b;
        tv_[tid] = (w != 0.0f) ? (-b / w) : 3.0e38f;  // sentinel: never crossed
    }
    __syncthreads();

    // stable rank-sort of 64 thresholds
    if (tid < HN) {
        float tv = tv_[tid];
        int r = 0;
        for (int j = 0; j < HN; j++) {
            float tj = tv_[j];
            r += (tj < tv) || (tj == tv && j < tid);
        }
        st[r] = tv;
        sidx[r] = tid;
    }
    __syncthreads();

    if (tid < HN) g_thr[f * HN + tid] = st[tid];

    // LUT scatter: lut[k] = #{thr : bucket(thr) < k} is a step function of k.
    // Thread t owns k in (bucket(st[t-1]), bucket(st[t])]; value = t.
    if (tid <= HN) {
        int blo = (tid == 0)  ? -1 : bucket_of(st[tid - 1]);
        int bhi = (tid == HN) ? NB : bucket_of(st[tid]);
        for (int k = blo + 1; k <= bhi && k <= NB; k++)
            slutc[k] = (unsigned char)tid;
    }

    // segment walk: 16 threads, one per e (all operands in smem)
    if (tid < EN) {
        int e = tid;
        const float* w2 = sv + e * HN;
        float A = 0.0f;
        float C = b2[f * EN + e];
        for (int h = 0; h < HN; h++) {
            float w = sw[h], b = sb[h], v = w2[h];
            float m = (w < 0.0f) ? 1.0f : 0.0f;            // active at x=-inf
            A += m * w * v;
            C += m * b * v;
            C += (w == 0.0f) ? fmaxf(b, 0.0f) * v : 0.0f;  // constant hinge
        }
        int grp = e >> 1, par = e & 1;
        for (int s = 0; s <= 64; s++) {
            stab[s * 32 + grp * 4 + par]     = A;
            stab[s * 32 + grp * 4 + 2 + par] = C;
            if (s < 64) {
                int h = sidx[s];
                float w = sw[h], b = sb[h], v = w2[h];
                float sg = (w > 0.0f) ? 1.0f : ((w < 0.0f) ? -1.0f : 0.0f);
                A += sg * w * v;
                C += sg * b * v;
            }
        }
    }
    __syncthreads();

    // LUT pair writeback
    for (int k = tid; k <= NB; k += 128) {
        unsigned char c0 = slutc[k];
        unsigned char c1 = (k < NB) ? slutc[k + 1] : c0;
        g_lutp[f * (NB + 1) + k] = make_uchar2(c0, c1);
    }

    // pack fp32 staging -> fp16 table, coalesced writeback
    for (int i = tid; i < 520; i += 128) {
        int s = i >> 3, j = i & 7;
        const float* p = stab + s * 32 + j * 4;
        h4 v;
        v.a = __floats2half2_rn(p[0], p[1]);
        v.c = __floats2half2_rn(p[2], p[3]);
        g_tab_h[f * 520 + i] = v;
    }
}

// ---------------------------------------------------------------------------
// Kernel 2: evaluation. Block = 4 features ("quad") x 512 rows, 256 threads.
// Warp owns 64 rows as 8 batches of 8.
// Phase 1: lane=(ff=lane>>3, rrow=lane&7): 32 distinct lookups (bucket LUT +
//   rare refinement). Double-buffered 32-slot exchange; ONE syncwarp/batch.
//   x prefetch runs 2 batches deep. Phase 2: lane=(ff, j=lane&7): 8 batched
//   broadcast LDS.64, then table LDS.64 in groups of 4, FMA, coalesced stcs.
// ---------------------------------------------------------------------------
__global__ void __launch_bounds__(256, 6) dfe_eval(
    const float* __restrict__ x, float* __restrict__ out)
{
    __shared__ h4     stab[4 * TAB_S];
    __shared__ float  sthr[4 * THR_S];
    __shared__ uchar2 slut[4 * LUT_S];
    __shared__ float2 sxch[8][2][32];    // per-warp double-buffered exchange

    int tid = threadIdx.x;
    int quad = blockIdx.x;
    int bbase = blockIdx.y * 512;

    #pragma unroll
    for (int ff = 0; ff < 4; ff++)
        for (int i = tid; i < 520; i += 256)
            stab[ff * TAB_S + i] = g_tab_h[(quad * 4 + ff) * 520 + i];
    for (int i = tid; i < 4 * 64; i += 256)
        sthr[(i >> 6) * THR_S + (i & 63)] = g_thr[quad * 256 + i];
    for (int i = tid; i < 4 * (NB + 1); i += 256) {
        int ff = i / (NB + 1), k = i % (NB + 1);
        slut[ff * LUT_S + k] = g_lutp[(quad * 4 + ff) * (NB + 1) + k];
    }
    __syncthreads();

    int lane = tid & 31, w = tid >> 5;
    int rrow = lane & 7;       // phase-1 row within batch
    int ff   = lane >> 3;      // feature within quad (both phases)
    int j    = lane & 7;       // phase-2 e-pair

    const float*  thrp = sthr + ff * THR_S;
    const uchar2* lutf = slut + ff * LUT_S;
    const h4*     tabf = stab + ff * TAB_S;

    int rb0 = bbase + w * 64;
    const float* xpb  = x   + (size_t)rb0 * FN + quad * 4 + ff;
    float*       outb = out + (size_t)rb0 * (FN * EN) + quad * 64 + ff * 16 + j * 2;

    auto seg_search = [&](float xs) -> int {
        int k = bucket_of(xs);
        uchar2 pr = lutf[k];
        int seg = pr.x;
        for (int t = pr.x; t < pr.y; t++) seg += (thrp[t] <= xs);
        return seg;   // exact count in [0,64]
    };

    // 2-deep pipeline: xs_c (current, searched), xs_n (loaded), + LDG in flight
    float xs_c = __ldg(xpb + (size_t)rrow * FN);
    float xs_n = __ldg(xpb + (size_t)(8 + rrow) * FN);
    int   seg_c = seg_search(xs_c);

    #pragma unroll
    for (int batch = 0; batch < 8; batch++) {
        float2* xch = sxch[w][batch & 1];
        xch[lane] = make_float2(xs_c, __int_as_float(seg_c));
        __syncwarp();

        // issue LDG for batch+2 immediately (lands during phase 2 + search)
        float xs_n2 = 0.0f;
        if (batch < 6)
            xs_n2 = __ldg(xpb + (size_t)((batch + 2) * 8 + rrow) * FN);

        float* orow = outb + (size_t)(batch * 8) * (FN * EN);
        int base = lane & 24;

        // batched exchange reads (8-deep broadcast LDS MLP)
        float2 e[8];
        #pragma unroll
        for (int r2 = 0; r2 < 8; r2++) e[r2] = xch[base | r2];

        // table reads + compute + store, groups of 4 (4-deep LDS MLP each)
        #pragma unroll
        for (int g = 0; g < 2; g++) {
            h4 v[4];
            #pragma unroll
            for (int q = 0; q < 4; q++)
                v[q] = tabf[__float_as_int(e[g * 4 + q].y) * 8 + j];
            #pragma unroll
            for (int q = 0; q < 4; q++) {
                int r2 = g * 4 + q;
                float2 a = __half22float2(v[q].a);
                float2 c = __half22float2(v[q].c);
                float2 o;
                o.x = fmaf(a.x, e[r2].x, c.x);
                o.y = fmaf(a.y, e[r2].x, c.y);
                __stcs((float2*)(orow + (size_t)r2 * (FN * EN)), o);
            }
        }

        // advance pipeline: search the already-landed xs_n
        if (batch < 7) {
            seg_c = seg_search(xs_n);
            xs_c = xs_n;
            xs_n = xs_n2;
        }
        // no second syncwarp: next batch writes the OTHER buffer; this buffer
        // is only rewritten 2 batches later, past the next syncwarp.
    }
}

extern "C" void kernel_launch(void* const* d_in, const int* in_sizes, int n_in,
                              void* d_out, int out_size)
{
    const float* x  = (const float*)d_in[0];
    const float* W1 = (const float*)d_in[1];
    const float* b1 = (const float*)d_in[2];
    const float* W2 = (const float*)d_in[3];
    const float* b2 = (const float*)d_in[4];
    float* out = (float*)d_out;

    dfe_precompute<<<FN, 128>>>(W1, b1, W2, b2);
    dfe_eval<<<dim3(FN / 4, BN / 512), 256>>>(x, out);
}